// round 2
// baseline (speedup 1.0000x reference)
#include <cuda_runtime.h>
#include <cstdint>

#define N_NODES  50000
#define N_EDGES  800000
#define N_GRAPHS 256
#define D_FEAT   96
#define HIDDEN   32

// Scratch (no cudaMalloc allowed)
__device__ float g_y[N_NODES * HIDDEN];     // x @ W1
__device__ float g_agg[N_NODES * HIDDEN];   // scatter-add accumulator
__device__ float g_pool[N_GRAPHS * HIDDEN]; // per-graph sums
__device__ float g_cnt[N_GRAPHS];           // per-graph node counts

// ---------------------------------------------------------------------------
// Kernel 1: y = x @ W1  (bias folded into kernel 3)
//           one warp per node; W1 (96x32) staged in shared.
//           Also zeroes g_agg rows; block 0 zeroes pool/cnt.
// ---------------------------------------------------------------------------
__global__ __launch_bounds__(256) void k1_gemm_y(
    const float* __restrict__ x, const float* __restrict__ W1)
{
    __shared__ float W1s[D_FEAT * HIDDEN]; // 12 KB
    const int tid  = threadIdx.x;
    const int lane = tid & 31;
    const int wid  = tid >> 5;

    for (int i = tid; i < D_FEAT * HIDDEN; i += 256)
        W1s[i] = W1[i];

    if (blockIdx.x == 0) {
        for (int i = tid; i < N_GRAPHS * HIDDEN; i += 256) g_pool[i] = 0.0f;
        if (tid < N_GRAPHS) g_cnt[tid] = 0.0f;
    }
    __syncthreads();

    const int node = blockIdx.x * 8 + wid;
    if (node >= N_NODES) return;

    const float xa = x[node * D_FEAT + lane];
    const float xb = x[node * D_FEAT + 32 + lane];
    const float xc = x[node * D_FEAT + 64 + lane];

    float acc = 0.0f;
#pragma unroll
    for (int f = 0; f < 32; f++) {
        acc += __shfl_sync(0xffffffffu, xa, f) * W1s[f * HIDDEN + lane];
        acc += __shfl_sync(0xffffffffu, xb, f) * W1s[(f + 32) * HIDDEN + lane];
        acc += __shfl_sync(0xffffffffu, xc, f) * W1s[(f + 64) * HIDDEN + lane];
    }
    g_y[node * HIDDEN + lane]   = acc;
    g_agg[node * HIDDEN + lane] = 0.0f;
}

// ---------------------------------------------------------------------------
// Kernel 2: edge scatter in 32-dim space.
//           one warp per edge: lane k: agg[dst][k] += y[src][k]
// ---------------------------------------------------------------------------
__global__ __launch_bounds__(256) void k2_scatter(
    const int* __restrict__ edge_index)
{
    const int lane = threadIdx.x & 31;
    const int e    = blockIdx.x * 8 + (threadIdx.x >> 5);
    if (e >= N_EDGES) return;

    const int s = edge_index[e];            // src
    const int d = edge_index[N_EDGES + e];  // dst

    const float v = g_y[s * HIDDEN + lane];
    atomicAdd(&g_agg[d * HIDDEN + lane], v);
}

// ---------------------------------------------------------------------------
// Kernel 3: per node: h = relu(agg + y + b1); h2 = relu(h @ W2 + b2);
//           pool[batch[node]] += h2 ; cnt[batch[node]] += 1
// ---------------------------------------------------------------------------
__global__ __launch_bounds__(256) void k3_mlp_pool(
    const float* __restrict__ b1, const float* __restrict__ W2,
    const float* __restrict__ b2, const int* __restrict__ batch)
{
    __shared__ float W2s[HIDDEN * HIDDEN]; // 4 KB
    const int tid  = threadIdx.x;
    const int lane = tid & 31;
    const int wid  = tid >> 5;

    for (int i = tid; i < HIDDEN * HIDDEN; i += 256)
        W2s[i] = W2[i];
    __syncthreads();

    const int node = blockIdx.x * 8 + wid;
    if (node >= N_NODES) return;

    float h = g_agg[node * HIDDEN + lane] + g_y[node * HIDDEN + lane] + b1[lane];
    h = fmaxf(h, 0.0f);

    float acc = 0.0f;
#pragma unroll
    for (int k = 0; k < 32; k++) {
        acc += __shfl_sync(0xffffffffu, h, k) * W2s[k * HIDDEN + lane];
    }
    acc += b2[lane];
    acc = fmaxf(acc, 0.0f);

    const int g = batch[node];
    atomicAdd(&g_pool[g * HIDDEN + lane], acc);
    if (lane == 0) atomicAdd(&g_cnt[g], 1.0f);
}

// ---------------------------------------------------------------------------
// Kernel 4: out[g] = (pool[g] / max(cnt[g],1)) @ Wc + bc   -> [256, 2]
// ---------------------------------------------------------------------------
__global__ __launch_bounds__(256) void k4_head(
    const float* __restrict__ Wc, const float* __restrict__ bc,
    float* __restrict__ out)
{
    const int g = threadIdx.x;
    if (g >= N_GRAPHS) return;

    const float inv = 1.0f / fmaxf(g_cnt[g], 1.0f);
    float o0 = 0.0f, o1 = 0.0f;
#pragma unroll
    for (int k = 0; k < HIDDEN; k++) {
        const float p = g_pool[g * HIDDEN + k] * inv;
        o0 += p * Wc[k * 2 + 0];
        o1 += p * Wc[k * 2 + 1];
    }
    out[g * 2 + 0] = o0 + bc[0];
    out[g * 2 + 1] = o1 + bc[1];
}

// ---------------------------------------------------------------------------
// launch
// inputs (metadata order): x, edge_index, batch, W1, b1, W2, b2, Wc, bc
// NOTE: edge_index/batch arrive as int32 (JAX x64 disabled downcasts int64).
// ---------------------------------------------------------------------------
extern "C" void kernel_launch(void* const* d_in, const int* in_sizes, int n_in,
                              void* d_out, int out_size)
{
    const float* x    = (const float*)d_in[0];
    const int*   ei   = (const int*)d_in[1];
    const int*   bat  = (const int*)d_in[2];
    const float* W1   = (const float*)d_in[3];
    const float* b1   = (const float*)d_in[4];
    const float* W2   = (const float*)d_in[5];
    const float* b2   = (const float*)d_in[6];
    const float* Wc   = (const float*)d_in[7];
    const float* bc   = (const float*)d_in[8];
    float*       out  = (float*)d_out;

    k1_gemm_y<<<(N_NODES + 7) / 8, 256>>>(x, W1);
    k2_scatter<<<(N_EDGES + 7) / 8, 256>>>(ei);
    k3_mlp_pool<<<(N_NODES + 7) / 8, 256>>>(b1, W2, b2, bat);
    k4_head<<<1, 256>>>(Wc, bc, out);
}

// round 3
// speedup vs baseline: 1.2068x; 1.2068x over previous
#include <cuda_runtime.h>
#include <cstdint>

#define N_NODES  50000
#define N_EDGES  800000
#define N_GRAPHS 256
#define D_FEAT   96
#define HIDDEN   32

// Scratch (no cudaMalloc allowed)
__device__ float g_y[N_NODES * HIDDEN];     // x @ W1
__device__ float g_agg[N_NODES * HIDDEN];   // scatter-add accumulator
__device__ float g_pool[N_GRAPHS * HIDDEN]; // per-graph sums
__device__ float g_cnt[N_GRAPHS];           // per-graph node counts
__device__ unsigned g_done;                 // k3 completion counter

// ---------------------------------------------------------------------------
// Kernel 1: y = x @ W1  (bias folded into kernel 3)
//           one warp per node; W1 (96x32) staged in shared.
//           Also zeroes g_agg rows; block 0 zeroes pool/cnt/done.
// ---------------------------------------------------------------------------
__global__ __launch_bounds__(256) void k1_gemm_y(
    const float* __restrict__ x, const float* __restrict__ W1)
{
    __shared__ float W1s[D_FEAT * HIDDEN]; // 12 KB
    const int tid  = threadIdx.x;
    const int lane = tid & 31;
    const int wid  = tid >> 5;

    for (int i = tid; i < D_FEAT * HIDDEN; i += 256)
        W1s[i] = W1[i];

    if (blockIdx.x == 0) {
        for (int i = tid; i < N_GRAPHS * HIDDEN; i += 256) g_pool[i] = 0.0f;
        if (tid < N_GRAPHS) g_cnt[tid] = 0.0f;
        if (tid == 0) g_done = 0u;
    }
    __syncthreads();

    const int node = blockIdx.x * 8 + wid;
    if (node >= N_NODES) return;

    const float xa = x[node * D_FEAT + lane];
    const float xb = x[node * D_FEAT + 32 + lane];
    const float xc = x[node * D_FEAT + 64 + lane];

    float acc = 0.0f;
#pragma unroll
    for (int f = 0; f < 32; f++) {
        acc += __shfl_sync(0xffffffffu, xa, f) * W1s[f * HIDDEN + lane];
        acc += __shfl_sync(0xffffffffu, xb, f) * W1s[(f + 32) * HIDDEN + lane];
        acc += __shfl_sync(0xffffffffu, xc, f) * W1s[(f + 64) * HIDDEN + lane];
    }
    g_y[node * HIDDEN + lane]   = acc;
    g_agg[node * HIDDEN + lane] = 0.0f;
}

// ---------------------------------------------------------------------------
// Kernel 2: edge scatter in 32-dim space, vectorized.
//           8 lanes per edge; each lane moves one float4 via red.global.v4.
//           One warp handles 4 edges.
// ---------------------------------------------------------------------------
__global__ __launch_bounds__(256) void k2_scatter(
    const int* __restrict__ edge_index)
{
    const int t     = blockIdx.x * 256 + threadIdx.x;
    const int e     = t >> 3;        // edge id (8 lanes per edge)
    const int sub   = t & 7;         // which float4 of the 32-float row
    if (e >= N_EDGES) return;

    const int s = __ldg(&edge_index[e]);            // src
    const int d = __ldg(&edge_index[N_EDGES + e]);  // dst

    const float4 v = *reinterpret_cast<const float4*>(&g_y[s * HIDDEN + sub * 4]);
    float* p = &g_agg[d * HIDDEN + sub * 4];
    asm volatile("red.global.add.v4.f32 [%0], {%1, %2, %3, %4};"
                 :: "l"(p), "f"(v.x), "f"(v.y), "f"(v.z), "f"(v.w)
                 : "memory");
}

// ---------------------------------------------------------------------------
// Kernel 3: per node: h = relu(agg + y + b1); h2 = relu(h @ W2 + b2);
//           pool[batch[node]] += h2 ; cnt[batch[node]] += 1.
//           Last block to finish runs the k4 head epilogue (fence+counter).
// ---------------------------------------------------------------------------
__global__ __launch_bounds__(256) void k3_mlp_pool(
    const float* __restrict__ b1, const float* __restrict__ W2,
    const float* __restrict__ b2, const int* __restrict__ batch,
    const float* __restrict__ Wc, const float* __restrict__ bc,
    float* __restrict__ out)
{
    __shared__ float W2s[HIDDEN * HIDDEN]; // 4 KB
    __shared__ bool amLast;
    const int tid  = threadIdx.x;
    const int lane = tid & 31;
    const int wid  = tid >> 5;

    for (int i = tid; i < HIDDEN * HIDDEN; i += 256)
        W2s[i] = W2[i];
    __syncthreads();

    const int node = blockIdx.x * 8 + wid;
    if (node < N_NODES) {
        float h = g_agg[node * HIDDEN + lane] + g_y[node * HIDDEN + lane] + b1[lane];
        h = fmaxf(h, 0.0f);

        float acc = 0.0f;
#pragma unroll
        for (int k = 0; k < 32; k++) {
            acc += __shfl_sync(0xffffffffu, h, k) * W2s[k * HIDDEN + lane];
        }
        acc += b2[lane];
        acc = fmaxf(acc, 0.0f);

        const int g = batch[node];
        atomicAdd(&g_pool[g * HIDDEN + lane], acc);
        if (lane == 0) atomicAdd(&g_cnt[g], 1.0f);
    }

    // ---- last-block epilogue (former k4) ----
    __threadfence();
    __syncthreads();
    if (tid == 0)
        amLast = (atomicAdd(&g_done, 1u) == gridDim.x - 1u);
    __syncthreads();

    if (amLast) {
        __threadfence();  // acquire: make all blocks' pool/cnt atomics visible
        const int g = tid; // 256 threads = 256 graphs
        const float inv = 1.0f / fmaxf(g_cnt[g], 1.0f);
        float o0 = 0.0f, o1 = 0.0f;
#pragma unroll
        for (int k = 0; k < HIDDEN; k++) {
            const float p = g_pool[g * HIDDEN + k] * inv;
            o0 += p * Wc[k * 2 + 0];
            o1 += p * Wc[k * 2 + 1];
        }
        out[g * 2 + 0] = o0 + bc[0];
        out[g * 2 + 1] = o1 + bc[1];
    }
}

// ---------------------------------------------------------------------------
// launch
// inputs (metadata order): x, edge_index, batch, W1, b1, W2, b2, Wc, bc
// edge_index/batch arrive as int32 (JAX x64 disabled downcasts int64).
// ---------------------------------------------------------------------------
extern "C" void kernel_launch(void* const* d_in, const int* in_sizes, int n_in,
                              void* d_out, int out_size)
{
    const float* x    = (const float*)d_in[0];
    const int*   ei   = (const int*)d_in[1];
    const int*   bat  = (const int*)d_in[2];
    const float* W1   = (const float*)d_in[3];
    const float* b1   = (const float*)d_in[4];
    const float* W2   = (const float*)d_in[5];
    const float* b2   = (const float*)d_in[6];
    const float* Wc   = (const float*)d_in[7];
    const float* bc   = (const float*)d_in[8];
    float*       out  = (float*)d_out;

    k1_gemm_y<<<(N_NODES + 7) / 8, 256>>>(x, W1);
    // 8 lanes per edge -> 32 threads handle 4 edges; 256-thread blocks do 32 edges
    k2_scatter<<<(N_EDGES * 8 + 255) / 256, 256>>>(ei);
    k3_mlp_pool<<<(N_NODES + 7) / 8, 256>>>(b1, W2, b2, bat, Wc, bc, out);
}

// round 4
// speedup vs baseline: 1.7797x; 1.4748x over previous
#include <cuda_runtime.h>
#include <cstdint>

#define N_NODES  50000
#define N_EDGES  800000
#define N_GRAPHS 256
#define D_FEAT   96
#define HIDDEN   32

#define XS_STRIDE 100   // 96 + 4 pad floats: node offsets {0,100,200,300} mod 32 distinct banks
#define HS_STRIDE 36    // 32 + 4 pad floats

// Scratch (no cudaMalloc allowed)
__device__ float g_y[N_NODES * HIDDEN];     // x @ W1
__device__ float g_agg[N_NODES * HIDDEN];   // scatter-add accumulator
__device__ float g_pool[N_GRAPHS * HIDDEN]; // per-graph sums
__device__ float g_cnt[N_GRAPHS];           // per-graph node counts
__device__ unsigned g_done;                 // k3 completion counter

// ---------------------------------------------------------------------------
// Kernel 1: y = x @ W1 (bias folded into k3). 32 nodes/block, 8 thr/node,
// 4 outputs/thread, all smem traffic as LDS.128. Zeroes agg; blk0 zeroes pool.
// ---------------------------------------------------------------------------
__global__ __launch_bounds__(256) void k1_gemm_y(
    const float* __restrict__ x, const float* __restrict__ W1)
{
    __shared__ float W1s[D_FEAT * HIDDEN];      // 12 KB, row f contiguous (32 floats)
    __shared__ float xs[32 * XS_STRIDE];        // 12.8 KB, padded rows

    const int tid = threadIdx.x;
    const int node0 = blockIdx.x * 32;

    // stage W1 (768 float4)
    {
        const float4* W14 = (const float4*)W1;
        float4* W1s4 = (float4*)W1s;
        for (int i = tid; i < D_FEAT * HIDDEN / 4; i += 256)
            W1s4[i] = W14[i];
    }
    // stage x for 32 nodes (768 float4), coalesced gmem reads
    {
        const float4* x4 = (const float4*)x;
        for (int i = tid; i < 32 * 24; i += 256) {       // 24 float4 per node
            const int nl = i / 24, fq = i % 24;
            const int node = node0 + nl;
            float4 v = make_float4(0.f, 0.f, 0.f, 0.f);
            if (node < N_NODES) v = x4[node * 24 + fq];
            *(float4*)&xs[nl * XS_STRIDE + fq * 4] = v;
        }
    }
    if (blockIdx.x == 0) {
        for (int i = tid; i < N_GRAPHS * HIDDEN; i += 256) g_pool[i] = 0.0f;
        if (tid < N_GRAPHS) g_cnt[tid] = 0.0f;
        if (tid == 0) g_done = 0u;
    }
    __syncthreads();

    const int nl   = tid >> 3;        // local node 0..31
    const int sub  = tid & 7;         // output quad 0..7
    const int node = node0 + nl;

    float4 acc = make_float4(0.f, 0.f, 0.f, 0.f);
#pragma unroll
    for (int fq = 0; fq < 24; fq++) {
        const float4 xv = *(const float4*)&xs[nl * XS_STRIDE + fq * 4];
        {
            const float4 wv = *(const float4*)&W1s[(fq * 4 + 0) * HIDDEN + sub * 4];
            acc.x += xv.x * wv.x; acc.y += xv.x * wv.y; acc.z += xv.x * wv.z; acc.w += xv.x * wv.w;
        }
        {
            const float4 wv = *(const float4*)&W1s[(fq * 4 + 1) * HIDDEN + sub * 4];
            acc.x += xv.y * wv.x; acc.y += xv.y * wv.y; acc.z += xv.y * wv.z; acc.w += xv.y * wv.w;
        }
        {
            const float4 wv = *(const float4*)&W1s[(fq * 4 + 2) * HIDDEN + sub * 4];
            acc.x += xv.z * wv.x; acc.y += xv.z * wv.y; acc.z += xv.z * wv.z; acc.w += xv.z * wv.w;
        }
        {
            const float4 wv = *(const float4*)&W1s[(fq * 4 + 3) * HIDDEN + sub * 4];
            acc.x += xv.w * wv.x; acc.y += xv.w * wv.y; acc.z += xv.w * wv.z; acc.w += xv.w * wv.w;
        }
    }
    if (node < N_NODES) {
        *(float4*)&g_y[node * HIDDEN + sub * 4]   = acc;
        *(float4*)&g_agg[node * HIDDEN + sub * 4] = make_float4(0.f, 0.f, 0.f, 0.f);
    }
}

// ---------------------------------------------------------------------------
// Kernel 2: edge scatter in 32-dim space; 8 lanes/edge, red.global.add.v4.f32
// ---------------------------------------------------------------------------
__global__ __launch_bounds__(256) void k2_scatter(
    const int* __restrict__ edge_index)
{
    const int t   = blockIdx.x * 256 + threadIdx.x;
    const int e   = t >> 3;
    const int sub = t & 7;
    if (e >= N_EDGES) return;

    const int s = __ldg(&edge_index[e]);            // src
    const int d = __ldg(&edge_index[N_EDGES + e]);  // dst

    const float4 v = *reinterpret_cast<const float4*>(&g_y[s * HIDDEN + sub * 4]);
    float* p = &g_agg[d * HIDDEN + sub * 4];
    asm volatile("red.global.add.v4.f32 [%0], {%1, %2, %3, %4};"
                 :: "l"(p), "f"(v.x), "f"(v.y), "f"(v.z), "f"(v.w)
                 : "memory");
}

// ---------------------------------------------------------------------------
// Kernel 3: h = relu(agg+y+b1); h2 = relu(h@W2+b2); pool via vector RED.
// Same float4 tiling as k1. Last-block epilogue does the head GEMV.
// ---------------------------------------------------------------------------
__global__ __launch_bounds__(256) void k3_mlp_pool(
    const float* __restrict__ b1, const float* __restrict__ W2,
    const float* __restrict__ b2, const int* __restrict__ batch,
    const float* __restrict__ Wc, const float* __restrict__ bc,
    float* __restrict__ out)
{
    __shared__ float W2s[HIDDEN * HIDDEN];   // 4 KB
    __shared__ float hs[32 * HS_STRIDE];     // 4.6 KB
    __shared__ bool amLast;

    const int tid = threadIdx.x;
    const int node0 = blockIdx.x * 32;

    {
        const float4* W24 = (const float4*)W2;
        float4* W2s4 = (float4*)W2s;
        for (int i = tid; i < HIDDEN * HIDDEN / 4; i += 256)
            W2s4[i] = W24[i];
    }

    const int nl   = tid >> 3;
    const int sub  = tid & 7;
    const int node = node0 + nl;

    // h = relu(agg + y + b1), staged to smem
    {
        float4 h = make_float4(0.f, 0.f, 0.f, 0.f);
        if (node < N_NODES) {
            const float4 a  = *(const float4*)&g_agg[node * HIDDEN + sub * 4];
            const float4 yv = *(const float4*)&g_y[node * HIDDEN + sub * 4];
            const float4 bv = *(const float4*)&b1[sub * 4];
            h.x = fmaxf(a.x + yv.x + bv.x, 0.f);
            h.y = fmaxf(a.y + yv.y + bv.y, 0.f);
            h.z = fmaxf(a.z + yv.z + bv.z, 0.f);
            h.w = fmaxf(a.w + yv.w + bv.w, 0.f);
        }
        *(float4*)&hs[nl * HS_STRIDE + sub * 4] = h;
    }
    __syncthreads();

    // h2 = relu(h @ W2 + b2)
    float4 acc = make_float4(0.f, 0.f, 0.f, 0.f);
#pragma unroll
    for (int kq = 0; kq < 8; kq++) {
        const float4 hv = *(const float4*)&hs[nl * HS_STRIDE + kq * 4];
        {
            const float4 wv = *(const float4*)&W2s[(kq * 4 + 0) * HIDDEN + sub * 4];
            acc.x += hv.x * wv.x; acc.y += hv.x * wv.y; acc.z += hv.x * wv.z; acc.w += hv.x * wv.w;
        }
        {
            const float4 wv = *(const float4*)&W2s[(kq * 4 + 1) * HIDDEN + sub * 4];
            acc.x += hv.y * wv.x; acc.y += hv.y * wv.y; acc.z += hv.y * wv.z; acc.w += hv.y * wv.w;
        }
        {
            const float4 wv = *(const float4*)&W2s[(kq * 4 + 2) * HIDDEN + sub * 4];
            acc.x += hv.z * wv.x; acc.y += hv.z * wv.y; acc.z += hv.z * wv.z; acc.w += hv.z * wv.w;
        }
        {
            const float4 wv = *(const float4*)&W2s[(kq * 4 + 3) * HIDDEN + sub * 4];
            acc.x += hv.w * wv.x; acc.y += hv.w * wv.y; acc.z += hv.w * wv.z; acc.w += hv.w * wv.w;
        }
    }

    if (node < N_NODES) {
        const float4 bv = *(const float4*)&b2[sub * 4];
        acc.x = fmaxf(acc.x + bv.x, 0.f);
        acc.y = fmaxf(acc.y + bv.y, 0.f);
        acc.z = fmaxf(acc.z + bv.z, 0.f);
        acc.w = fmaxf(acc.w + bv.w, 0.f);

        const int g = batch[node];
        float* p = &g_pool[g * HIDDEN + sub * 4];
        asm volatile("red.global.add.v4.f32 [%0], {%1, %2, %3, %4};"
                     :: "l"(p), "f"(acc.x), "f"(acc.y), "f"(acc.z), "f"(acc.w)
                     : "memory");
        if (sub == 0) atomicAdd(&g_cnt[g], 1.0f);
    }

    // ---- last-block epilogue (head) ----
    __threadfence();
    __syncthreads();
    if (tid == 0)
        amLast = (atomicAdd(&g_done, 1u) == gridDim.x - 1u);
    __syncthreads();

    if (amLast) {
        __threadfence();
        const int g = tid; // 256 threads = 256 graphs
        const float inv = 1.0f / fmaxf(g_cnt[g], 1.0f);
        float o0 = 0.0f, o1 = 0.0f;
#pragma unroll
        for (int k = 0; k < HIDDEN; k++) {
            const float p = g_pool[g * HIDDEN + k] * inv;
            o0 += p * Wc[k * 2 + 0];
            o1 += p * Wc[k * 2 + 1];
        }
        out[g * 2 + 0] = o0 + bc[0];
        out[g * 2 + 1] = o1 + bc[1];
    }
}

// ---------------------------------------------------------------------------
// launch — inputs: x, edge_index, batch, W1, b1, W2, b2, Wc, bc (idx int32)
// ---------------------------------------------------------------------------
extern "C" void kernel_launch(void* const* d_in, const int* in_sizes, int n_in,
                              void* d_out, int out_size)
{
    const float* x    = (const float*)d_in[0];
    const int*   ei   = (const int*)d_in[1];
    const int*   bat  = (const int*)d_in[2];
    const float* W1   = (const float*)d_in[3];
    const float* b1   = (const float*)d_in[4];
    const float* W2   = (const float*)d_in[5];
    const float* b2   = (const float*)d_in[6];
    const float* Wc   = (const float*)d_in[7];
    const float* bc   = (const float*)d_in[8];
    float*       out  = (float*)d_out;

    k1_gemm_y<<<(N_NODES + 31) / 32, 256>>>(x, W1);
    k2_scatter<<<(N_EDGES * 8 + 255) / 256, 256>>>(ei);
    k3_mlp_pool<<<(N_NODES + 31) / 32, 256>>>(b1, W2, b2, bat, Wc, bc, out);
}